// round 2
// baseline (speedup 1.0000x reference)
#include <cuda_runtime.h>
#include <math_constants.h>

#define BB 2
#define LL 2048
#define NH 16
#define DD 64
#define SCALE 0.125f
#define NEGINF -1.0e9f

// scratch for softmax stats: [B*L*NH] each
__device__ float g_m[BB * LL * NH];
__device__ float g_rl[BB * LL * NH];

// ---------------------------------------------------------------------------
// Kernel 1: raw masked scaled scores -> attn buffer [B][L_i][L_j][NH]
// CTA: (j-tile 32, i-tile 16, b). 512 threads = 16 warps; warp w = head n.
// Each lane: 4x4 micro-tile of (ii, jj). D processed in 2 chunks of 32.
// ---------------------------------------------------------------------------
__global__ __launch_bounds__(512) void k_scores(
    const float* __restrict__ q, const float* __restrict__ k,
    const int* __restrict__ mask, float* __restrict__ attn)
{
    extern __shared__ float smem[];
    float* Qs = smem;               // [16 n][16 ii][33]
    float* Ks = smem + 16 * 16 * 33; // [16 n][32 jj][33]

    const int b  = blockIdx.z;
    const int i0 = blockIdx.y * 16;
    const int j0 = blockIdx.x * 32;
    const int tid  = threadIdx.x;
    const int n    = tid >> 5;
    const int lane = tid & 31;
    const int ii0 = (lane >> 3) * 4;  // 4 groups
    const int jj0 = (lane & 7) * 4;   // 8 groups

    float acc[4][4];
#pragma unroll
    for (int u = 0; u < 4; u++)
#pragma unroll
        for (int v = 0; v < 4; v++) acc[u][v] = 0.f;

    for (int dc = 0; dc < DD; dc += 32) {
        __syncthreads();
        // load Q chunk: 16*16*32 floats, coalesced over d
        for (int idx = tid; idx < 16 * 16 * 32; idx += 512) {
            int d = idx & 31; int nn = (idx >> 5) & 15; int ii = idx >> 9;
            Qs[(nn * 16 + ii) * 33 + d] =
                q[(((size_t)(b * LL + i0 + ii)) * NH + nn) * DD + dc + d];
        }
        // load K chunk: 16*32*32 floats
        for (int idx = tid; idx < 16 * 32 * 32; idx += 512) {
            int d = idx & 31; int nn = (idx >> 5) & 15; int jj = idx >> 9;
            Ks[(nn * 32 + jj) * 33 + d] =
                k[(((size_t)(b * LL + j0 + jj)) * NH + nn) * DD + dc + d];
        }
        __syncthreads();

#pragma unroll 8
        for (int d = 0; d < 32; d++) {
            float qa[4], kb[4];
#pragma unroll
            for (int u = 0; u < 4; u++) qa[u] = Qs[(n * 16 + ii0 + u) * 33 + d];
#pragma unroll
            for (int v = 0; v < 4; v++) kb[v] = Ks[(n * 32 + jj0 + v) * 33 + d];
#pragma unroll
            for (int u = 0; u < 4; u++)
#pragma unroll
                for (int v = 0; v < 4; v++) acc[u][v] += qa[u] * kb[v];
        }
    }

#pragma unroll
    for (int u = 0; u < 4; u++) {
        int i = i0 + ii0 + u;
#pragma unroll
        for (int v = 0; v < 4; v++) {
            int j = j0 + jj0 + v;
            float s = acc[u][v] * SCALE;
            if (mask[(size_t)(b * LL + i) * LL + j] != 0) s = NEGINF;
            attn[(((size_t)(b * LL + i)) * LL + j) * NH + n] = s;
        }
    }
}

// ---------------------------------------------------------------------------
// Kernel 2: per-row (b,i,n) online max/sum over j. CTA per (b,i), 512 thr.
// thread's head n = tid % 16 is constant (512 % 16 == 0), coalesced reads.
// ---------------------------------------------------------------------------
__global__ __launch_bounds__(512) void k_stats(const float* __restrict__ attn)
{
    const int bi = blockIdx.x;
    const int tid = threadIdx.x;
    const size_t base = (size_t)bi * (LL * NH);

    float m = -CUDART_INF_F, l = 0.f;
    for (int idx = tid; idx < LL * NH; idx += 512) {
        float x = attn[base + idx];
        if (x > m) { l = l * __expf(m - x) + 1.f; m = x; }
        else       { l += __expf(x - m); }
    }
    // combine lane n with lane n+16 (same row)
    {
        float m2 = __shfl_xor_sync(0xffffffffu, m, 16);
        float l2 = __shfl_xor_sync(0xffffffffu, l, 16);
        if (m2 > m) { l = l * __expf(m - m2) + l2; m = m2; }
        else        { l = l + l2 * __expf(m2 - m); }
    }
    __shared__ float smm[16][16], sll[16][16];
    const int w = tid >> 5, lane = tid & 31;
    if (lane < 16) { smm[w][lane] = m; sll[w][lane] = l; }
    __syncthreads();
    if (tid < 16) {
        float M = smm[0][tid], Lc = sll[0][tid];
#pragma unroll
        for (int w2 = 1; w2 < 16; w2++) {
            float m2 = smm[w2][tid], l2 = sll[w2][tid];
            if (m2 > M) { Lc = Lc * __expf(M - m2) + l2; M = m2; }
            else        { Lc += l2 * __expf(m2 - M); }
        }
        g_m[bi * 16 + tid]  = M;
        g_rl[bi * 16 + tid] = 1.f / Lc;
    }
}

// ---------------------------------------------------------------------------
// Kernel 3: normalize probs in place (final attention output) + context = P@V.
// CTA per (b, i-tile 16). 512 threads: thread = (n = tid/32, d-pair = tid%32).
// acc: 16 ii x float2. V staged per 16-j chunk in smem (64 KB).
// ---------------------------------------------------------------------------
__global__ __launch_bounds__(512) void k_pv(
    float* __restrict__ attn, const float* __restrict__ v,
    float* __restrict__ ctx)
{
    extern __shared__ float smem[];
    float* Ps = smem;            // [16 ii][16 jj][16 n]
    float* Vs = Ps + 4096;       // [16 jj][16 n][64 d]
    float* Ms = Vs + 16384;      // [16 ii][16 n]
    float* Rs = Ms + 256;        // [16 ii][16 n]

    const int b  = blockIdx.y;
    const int i0 = blockIdx.x * 16;
    const int tid = threadIdx.x;

    if (tid < 256) {
        int ii = tid >> 4, n = tid & 15;
        Ms[tid] = g_m[(size_t)(b * LL + i0 + ii) * NH + n];
        Rs[tid] = g_rl[(size_t)(b * LL + i0 + ii) * NH + n];
    }

    const int n  = tid >> 5;
    const int dh = tid & 31;  // owns d = 2*dh, 2*dh+1
    float2 acc[16];
#pragma unroll
    for (int u = 0; u < 16; u++) acc[u] = make_float2(0.f, 0.f);

    __syncthreads();

    for (int j0 = 0; j0 < LL; j0 += 16) {
        // p = exp(s - m) * (1/l); write back (final attention), stage in smem
        for (int idx = tid; idx < 4096; idx += 512) {
            int nn = idx & 15; int jj = (idx >> 4) & 15; int ii = idx >> 8;
            size_t g = (((size_t)(b * LL + i0 + ii)) * LL + j0 + jj) * NH + nn;
            float p = __expf(attn[g] - Ms[ii * 16 + nn]) * Rs[ii * 16 + nn];
            attn[g] = p;
            Ps[(ii * 16 + jj) * 16 + nn] = p;
        }
        // stage V tile [16 jj][16 n][64 d]
        for (int idx = tid; idx < 16384; idx += 512) {
            int d = idx & 63; int nn = (idx >> 6) & 15; int jj = idx >> 10;
            Vs[(jj * 16 + nn) * 64 + d] =
                v[(((size_t)(b * LL + j0 + jj)) * NH + nn) * DD + d];
        }
        __syncthreads();

        const float2* V2 = (const float2*)Vs;
#pragma unroll 4
        for (int jj = 0; jj < 16; jj++) {
            float2 vv = V2[(jj * 16 + n) * 32 + dh];
#pragma unroll
            for (int ii = 0; ii < 16; ii++) {
                float p = Ps[(ii * 16 + jj) * 16 + n];
                acc[ii].x += p * vv.x;
                acc[ii].y += p * vv.y;
            }
        }
        __syncthreads();
    }

#pragma unroll
    for (int ii = 0; ii < 16; ii++) {
        size_t g = (((size_t)(b * LL + i0 + ii)) * NH + n) * DD + dh * 2;
        *(float2*)(ctx + g) = acc[ii];
    }
}

// ---------------------------------------------------------------------------
extern "C" void kernel_launch(void* const* d_in, const int* in_sizes, int n_in,
                              void* d_out, int out_size)
{
    const float* q = (const float*)d_in[0];
    const float* k = (const float*)d_in[1];
    const float* v = (const float*)d_in[2];
    const int* mask = (const int*)d_in[3];

    float* ctx  = (float*)d_out;
    float* attn = (float*)d_out + (size_t)BB * LL * NH * DD;

    const int smem1 = (16 * 16 * 33 + 16 * 32 * 33) * 4;   // 101376 B
    const int smem3 = (4096 + 16384 + 256 + 256) * 4;      // 83968 B
    cudaFuncSetAttribute(k_scores, cudaFuncAttributeMaxDynamicSharedMemorySize, smem1);
    cudaFuncSetAttribute(k_pv,     cudaFuncAttributeMaxDynamicSharedMemorySize, smem3);

    dim3 g1(LL / 32, LL / 16, BB);
    k_scores<<<g1, 512, smem1>>>(q, k, mask, attn);

    k_stats<<<BB * LL, 512>>>(attn);

    dim3 g3(LL / 16, BB);
    k_pv<<<g3, 512, smem3>>>(attn, v, ctx);
}

// round 3
// speedup vs baseline: 1.1943x; 1.1943x over previous
#include <cuda_runtime.h>
#include <math_constants.h>

#define BB 2
#define LL 2048
#define NH 16
#define DD 64
#define SCALE 0.125f
#define NEGINF -1.0e9f

// scratch for softmax stats: [B*L*NH] each
__device__ float g_m[BB * LL * NH];
__device__ float g_rl[BB * LL * NH];

// ---------------------------------------------------------------------------
// Kernel 1: raw masked scaled scores -> attn buffer [B][L_i][L_j][NH]
// CTA: (j-tile 32, i-tile 16, b). 512 threads = 16 warps; warp = head n.
// Lane: 4x4 micro-tile. d in 2 chunks of 32, float4 LDS with XOR swizzle.
// Epilogue staged in smem for coalesced global stores.
// ---------------------------------------------------------------------------
__global__ __launch_bounds__(512, 2) void k_scores(
    const float* __restrict__ q, const float* __restrict__ k,
    const int* __restrict__ mask, float* __restrict__ attn)
{
    extern __shared__ float smem[];
    float* Qs = smem;           // [16 n][16 ii][32] swizzled
    float* Ks = smem + 8192;    // [16 n][32 jj][32] swizzled
    __shared__ int Msk[512];    // [16 ii][32 jj]

    const int b  = blockIdx.z;
    const int i0 = blockIdx.y * 16;
    const int j0 = blockIdx.x * 32;
    const int tid  = threadIdx.x;
    const int n    = tid >> 5;
    const int lane = tid & 31;
    const int ii0 = (lane >> 3) * 4;  // {0,4,8,12}
    const int jj0 = (lane & 7) * 4;   // {0,4,...,28}

    // mask tile (coalesced, once)
    Msk[tid] = mask[((size_t)(b * LL + i0 + (tid >> 5))) * LL + j0 + (tid & 31)];

    float acc[4][4];
#pragma unroll
    for (int u = 0; u < 4; u++)
#pragma unroll
        for (int v = 0; v < 4; v++) acc[u][v] = 0.f;

    for (int dc = 0; dc < DD; dc += 32) {
        __syncthreads();
        // Q chunk: 8192 floats, swizzled store (conflict-free)
        for (int idx = tid; idx < 8192; idx += 512) {
            int d = idx & 31; int nn = (idx >> 5) & 15; int ii = idx >> 9;
            int g = (d >> 2) ^ (ii >> 2);
            Qs[(nn * 16 + ii) * 32 + g * 4 + (d & 3)] =
                q[(((size_t)(b * LL + i0 + ii)) * NH + nn) * DD + dc + d];
        }
        // K chunk: 16384 floats
        for (int idx = tid; idx < 16384; idx += 512) {
            int d = idx & 31; int nn = (idx >> 5) & 15; int jj = idx >> 9;
            int g = (d >> 2) ^ (jj >> 2);
            Ks[(nn * 32 + jj) * 32 + g * 4 + (d & 3)] =
                k[(((size_t)(b * LL + j0 + jj)) * NH + nn) * DD + dc + d];
        }
        __syncthreads();

#pragma unroll
        for (int g = 0; g < 8; g++) {
            float4 qa[4], kb[4];
#pragma unroll
            for (int u = 0; u < 4; u++)
                qa[u] = *(const float4*)&Qs[(n * 16 + ii0 + u) * 32 +
                                            ((g ^ ((ii0 + u) >> 2)) << 2)];
#pragma unroll
            for (int v = 0; v < 4; v++)
                kb[v] = *(const float4*)&Ks[(n * 32 + jj0 + v) * 32 +
                                            ((g ^ ((jj0 + v) >> 2)) << 2)];
#pragma unroll
            for (int u = 0; u < 4; u++)
#pragma unroll
                for (int v = 0; v < 4; v++) {
                    acc[u][v] += qa[u].x * kb[v].x;
                    acc[u][v] += qa[u].y * kb[v].y;
                    acc[u][v] += qa[u].z * kb[v].z;
                    acc[u][v] += qa[u].w * kb[v].w;
                }
        }
    }

    // stage masked scaled scores in smem (reuse Qs/Ks space), pitch 17 over n
    __syncthreads();
    float* Ss = smem;  // [16 ii][32 jj][17]
#pragma unroll
    for (int u = 0; u < 4; u++)
#pragma unroll
        for (int v = 0; v < 4; v++) {
            int il = ii0 + u, jl = jj0 + v;
            float s = acc[u][v] * SCALE;
            if (Msk[il * 32 + jl] != 0) s = NEGINF;
            Ss[(il * 32 + jl) * 17 + n] = s;
        }
    __syncthreads();

    // coalesced global store: contiguous 2KB per i row
    for (int idx = tid; idx < 8192; idx += 512) {
        int nn = idx & 15; int jj = (idx >> 4) & 31; int ii = idx >> 9;
        attn[(((size_t)(b * LL + i0 + ii)) * LL + j0 + jj) * NH + nn] =
            Ss[(ii * 32 + jj) * 17 + nn];
    }
}

// ---------------------------------------------------------------------------
// Kernel 2: per-row (b,i,n) online max/sum over j. CTA per (b,i), 512 thr.
// ---------------------------------------------------------------------------
__global__ __launch_bounds__(512) void k_stats(const float* __restrict__ attn)
{
    const int bi = blockIdx.x;
    const int tid = threadIdx.x;
    const size_t base = (size_t)bi * (LL * NH);

    float m = -CUDART_INF_F, l = 0.f;
    for (int idx = tid; idx < LL * NH; idx += 512) {
        float x = attn[base + idx];
        if (x > m) { l = l * __expf(m - x) + 1.f; m = x; }
        else       { l += __expf(x - m); }
    }
    {
        float m2 = __shfl_xor_sync(0xffffffffu, m, 16);
        float l2 = __shfl_xor_sync(0xffffffffu, l, 16);
        if (m2 > m) { l = l * __expf(m - m2) + l2; m = m2; }
        else        { l = l + l2 * __expf(m2 - m); }
    }
    __shared__ float smm[16][16], sll[16][16];
    const int w = tid >> 5, lane = tid & 31;
    if (lane < 16) { smm[w][lane] = m; sll[w][lane] = l; }
    __syncthreads();
    if (tid < 16) {
        float M = smm[0][tid], Lc = sll[0][tid];
#pragma unroll
        for (int w2 = 1; w2 < 16; w2++) {
            float m2 = smm[w2][tid], l2 = sll[w2][tid];
            if (m2 > M) { Lc = Lc * __expf(M - m2) + l2; M = m2; }
            else        { Lc += l2 * __expf(m2 - M); }
        }
        g_m[bi * 16 + tid]  = M;
        g_rl[bi * 16 + tid] = 1.f / Lc;
    }
}

// ---------------------------------------------------------------------------
// Kernel 3: normalize probs in place + context = P@V.
// CTA per (b, i-tile 16). 512 threads: warp = head n; lane = (dq 0..15, hs).
// Thread: 8 ii (hs half) x 4 d (float4). Ps transposed [jj][n][ii] pitch 20.
// ---------------------------------------------------------------------------
__global__ __launch_bounds__(512, 2) void k_pv(
    float* __restrict__ attn, const float* __restrict__ v,
    float* __restrict__ ctx)
{
    extern __shared__ float smem[];
    float* Ps = smem;             // [16 jj][16 n][20] (ii padded 16->20)
    float* Vs = Ps + 5120;        // [16 jj][16 n][64 d]
    float* Ms = Vs + 16384;       // [16 ii][16 n]
    float* Rs = Ms + 256;

    const int b  = blockIdx.y;
    const int i0 = blockIdx.x * 16;
    const int tid = threadIdx.x;

    if (tid < 256) {
        int ii = tid >> 4, nn = tid & 15;
        Ms[tid] = g_m[(size_t)(b * LL + i0 + ii) * NH + nn];
        Rs[tid] = g_rl[(size_t)(b * LL + i0 + ii) * NH + nn];
    }

    const int n  = tid >> 5;
    const int lane = tid & 31;
    const int dq = lane & 15;     // d block: 4 floats at dq*4
    const int hs = lane >> 4;     // ii half: hs*8 .. hs*8+7

    float4 acc[8];
#pragma unroll
    for (int r = 0; r < 8; r++) acc[r] = make_float4(0.f, 0.f, 0.f, 0.f);

    __syncthreads();

    for (int j0 = 0; j0 < LL; j0 += 16) {
        // p = exp(s-m)/l; write back final attention; stage transposed
        for (int idx = tid; idx < 4096; idx += 512) {
            int nn = idx & 15; int jj = (idx >> 4) & 15; int ii = idx >> 8;
            size_t g = (((size_t)(b * LL + i0 + ii)) * LL + j0 + jj) * NH + nn;
            float p = __expf(attn[g] - Ms[ii * 16 + nn]) * Rs[ii * 16 + nn];
            attn[g] = p;
            Ps[(jj * 16 + nn) * 20 + ii] = p;
        }
        // stage V tile [16 jj][16 n][64 d] (coalesced, conflict-free)
        for (int idx = tid; idx < 16384; idx += 512) {
            int d = idx & 63; int nn = (idx >> 6) & 15; int jj = idx >> 10;
            Vs[(jj * 16 + nn) * 64 + d] =
                v[(((size_t)(b * LL + j0 + jj)) * NH + nn) * DD + d];
        }
        __syncthreads();

#pragma unroll 4
        for (int jj = 0; jj < 16; jj++) {
            const float* pr = &Ps[(jj * 16 + n) * 20 + hs * 8];
            float4 p0 = *(const float4*)(pr);
            float4 p1 = *(const float4*)(pr + 4);
            float4 vv = *(const float4*)&Vs[(jj * 16 + n) * 64 + dq * 4];
            acc[0].x += p0.x * vv.x; acc[0].y += p0.x * vv.y; acc[0].z += p0.x * vv.z; acc[0].w += p0.x * vv.w;
            acc[1].x += p0.y * vv.x; acc[1].y += p0.y * vv.y; acc[1].z += p0.y * vv.z; acc[1].w += p0.y * vv.w;
            acc[2].x += p0.z * vv.x; acc[2].y += p0.z * vv.y; acc[2].z += p0.z * vv.z; acc[2].w += p0.z * vv.w;
            acc[3].x += p0.w * vv.x; acc[3].y += p0.w * vv.y; acc[3].z += p0.w * vv.z; acc[3].w += p0.w * vv.w;
            acc[4].x += p1.x * vv.x; acc[4].y += p1.x * vv.y; acc[4].z += p1.x * vv.z; acc[4].w += p1.x * vv.w;
            acc[5].x += p1.y * vv.x; acc[5].y += p1.y * vv.y; acc[5].z += p1.y * vv.z; acc[5].w += p1.y * vv.w;
            acc[6].x += p1.z * vv.x; acc[6].y += p1.z * vv.y; acc[6].z += p1.z * vv.z; acc[6].w += p1.z * vv.w;
            acc[7].x += p1.w * vv.x; acc[7].y += p1.w * vv.y; acc[7].z += p1.w * vv.z; acc[7].w += p1.w * vv.w;
        }
        __syncthreads();
    }

#pragma unroll
    for (int r = 0; r < 8; r++) {
        int ii = hs * 8 + r;
        size_t g = (((size_t)(b * LL + i0 + ii)) * NH + n) * DD + dq * 4;
        *(float4*)(ctx + g) = acc[r];
    }
}

// ---------------------------------------------------------------------------
extern "C" void kernel_launch(void* const* d_in, const int* in_sizes, int n_in,
                              void* d_out, int out_size)
{
    const float* q = (const float*)d_in[0];
    const float* k = (const float*)d_in[1];
    const float* v = (const float*)d_in[2];
    const int* mask = (const int*)d_in[3];

    float* ctx  = (float*)d_out;
    float* attn = (float*)d_out + (size_t)BB * LL * NH * DD;

    const int smem1 = (8192 + 16384) * 4;                  // 96 KB
    const int smem3 = (5120 + 16384 + 256 + 256) * 4;      // ~88 KB
    cudaFuncSetAttribute(k_scores, cudaFuncAttributeMaxDynamicSharedMemorySize, smem1);
    cudaFuncSetAttribute(k_pv,     cudaFuncAttributeMaxDynamicSharedMemorySize, smem3);

    dim3 g1(LL / 32, LL / 16, BB);
    k_scores<<<g1, 512, smem1>>>(q, k, mask, attn);

    k_stats<<<BB * LL, 512>>>(attn);

    dim3 g3(LL / 16, BB);
    k_pv<<<g3, 512, smem3>>>(attn, v, ctx);
}

// round 4
// speedup vs baseline: 1.3560x; 1.1353x over previous
#include <cuda_runtime.h>
#include <math_constants.h>

#define BB 2
#define LL 2048
#define NH 16
#define DD 64
#define SCALE 0.125f
#define NEGINF -1.0e9f

#define NTJ 64                   // number of j-tiles (2048/32)
#define NROWS (BB * NH * LL)     // 65536 softmax rows

// per-(row, j-tile) partial softmax stats, layout [jt][b][n][i]
__device__ float g_tm[NTJ * NROWS];
__device__ float g_tl[NTJ * NROWS];
// final stats, layout [b][i][n]
__device__ float g_m[BB * LL * NH];
__device__ float g_rl[BB * LL * NH];

// ---------------------------------------------------------------------------
// Kernel 1: masked scaled scores -> attn buffer [B][L_i][L_j][NH]
//           + per-tile softmax (max, sumexp) into g_tm/g_tl.
// CTA: 256 thr = 8 warps = 8 heads; tile 32i x 32j; z = b*2 + head-half.
// Lane: 4i x 8j micro-tile; float4 LDS with hoisted XOR swizzle.
// ---------------------------------------------------------------------------
__global__ __launch_bounds__(256, 2) void k_scores(
    const float* __restrict__ q, const float* __restrict__ k,
    const int* __restrict__ mask, float* __restrict__ attn)
{
    extern __shared__ float smem[];
    float* Qs = smem;           // [8 w][32 ii][32 d] swizzled
    float* Ks = smem + 8192;    // [8 w][32 jj][32 d] swizzled
    __shared__ int Msk[1024];   // [32 ii][32 jj]

    const int b  = blockIdx.z >> 1;
    const int nb = (blockIdx.z & 1) * 8;
    const int i0 = blockIdx.y * 32;
    const int j0 = blockIdx.x * 32;
    const int jt = blockIdx.x;
    const int tid  = threadIdx.x;
    const int w    = tid >> 5;        // local head
    const int n    = nb + w;          // global head
    const int lane = tid & 31;
    const int ii_g = lane & 7;  const int ii0 = ii_g * 4;  // 4 rows
    const int jj_g = lane >> 3; const int jj0 = jj_g * 8;  // 8 cols
    const int cq  = ii_g;             // Q swizzle const (all 4 rows)
    const int ck0 = jj_g * 2;         // K swizzle const rows v=0..3
    const int ck1 = jj_g * 2 + 1;     // K swizzle const rows v=4..7

    for (int idx = tid; idx < 1024; idx += 256)
        Msk[idx] = mask[((size_t)(b * LL + i0 + (idx >> 5))) * LL + j0 + (idx & 31)];

    float acc[4][8];
#pragma unroll
    for (int u = 0; u < 4; u++)
#pragma unroll
        for (int v = 0; v < 8; v++) acc[u][v] = 0.f;

#pragma unroll
    for (int dc = 0; dc < DD; dc += 32) {
        __syncthreads();
        // Q chunk: 2048 float4 (8 heads x 32 rows x 8 f4)
        for (int idx = tid; idx < 2048; idx += 256) {
            int d4 = idx & 7; int nn = (idx >> 3) & 7; int ii = idx >> 6;
            float4 val = *(const float4*)&q[
                (((size_t)(b * LL + i0 + ii)) * NH + nb + nn) * DD + dc + d4 * 4];
            *(float4*)&Qs[(nn * 32 + ii) * 32 + ((d4 ^ (ii >> 2)) << 2)] = val;
        }
        // K chunk
        for (int idx = tid; idx < 2048; idx += 256) {
            int d4 = idx & 7; int nn = (idx >> 3) & 7; int jj = idx >> 6;
            float4 val = *(const float4*)&k[
                (((size_t)(b * LL + j0 + jj)) * NH + nb + nn) * DD + dc + d4 * 4];
            *(float4*)&Ks[(nn * 32 + jj) * 32 + ((d4 ^ (jj >> 2)) << 2)] = val;
        }
        __syncthreads();

        const float* qb = Qs + (w * 32 + ii0) * 32;
        const float* kb = Ks + (w * 32 + jj0) * 32;
#pragma unroll
        for (int g = 0; g < 8; g++) {
            const float4* qp  = (const float4*)(qb + ((g ^ cq)  << 2));
            const float4* kp0 = (const float4*)(kb + ((g ^ ck0) << 2));
            const float4* kp1 = (const float4*)(kb + 128 + ((g ^ ck1) << 2));
            float4 qa[4], kv[8];
#pragma unroll
            for (int u = 0; u < 4; u++) qa[u] = qp[u * 8];
#pragma unroll
            for (int v = 0; v < 4; v++) kv[v] = kp0[v * 8];
#pragma unroll
            for (int v = 0; v < 4; v++) kv[4 + v] = kp1[v * 8];
#pragma unroll
            for (int u = 0; u < 4; u++)
#pragma unroll
                for (int v = 0; v < 8; v++) {
                    acc[u][v] += qa[u].x * kv[v].x;
                    acc[u][v] += qa[u].y * kv[v].y;
                    acc[u][v] += qa[u].z * kv[v].z;
                    acc[u][v] += qa[u].w * kv[v].w;
                }
        }
    }

    // scale + mask + per-tile stats (reduce over 32 j within tile)
    float mrow[4], lrow[4];
#pragma unroll
    for (int u = 0; u < 4; u++) {
        float mm = -CUDART_INF_F;
#pragma unroll
        for (int v = 0; v < 8; v++) {
            float s = acc[u][v] * SCALE;
            if (Msk[(ii0 + u) * 32 + jj0 + v] != 0) s = NEGINF;
            acc[u][v] = s;
            mm = fmaxf(mm, s);
        }
        mm = fmaxf(mm, __shfl_xor_sync(0xffffffffu, mm, 8));
        mm = fmaxf(mm, __shfl_xor_sync(0xffffffffu, mm, 16));
        float ll = 0.f;
#pragma unroll
        for (int v = 0; v < 8; v++) ll += __expf(acc[u][v] - mm);
        ll += __shfl_xor_sync(0xffffffffu, ll, 8);
        ll += __shfl_xor_sync(0xffffffffu, ll, 16);
        mrow[u] = mm; lrow[u] = ll;
    }
    if (jj_g == 0) {
#pragma unroll
        for (int u = 0; u < 4; u++) {
            size_t r = ((size_t)(b * NH + n)) * LL + i0 + ii0 + u;
            g_tm[(size_t)jt * NROWS + r] = mrow[u];
            g_tl[(size_t)jt * NROWS + r] = lrow[u];
        }
    }

    // stage in smem and store coalesced
    __syncthreads();
    float* Ss = smem;  // [32 ii][32 jj][pitch 9], 9216 floats
#pragma unroll
    for (int u = 0; u < 4; u++)
#pragma unroll
        for (int v = 0; v < 8; v++)
            Ss[((ii0 + u) * 32 + jj0 + v) * 9 + w] = acc[u][v];
    __syncthreads();

    for (int idx = tid; idx < 8192; idx += 256) {
        int nn = idx & 7; int jj = (idx >> 3) & 31; int ii = idx >> 8;
        attn[(((size_t)(b * LL + i0 + ii)) * LL + j0 + jj) * NH + nb + nn] =
            Ss[(ii * 32 + jj) * 9 + nn];
    }
}

// ---------------------------------------------------------------------------
// Kernel 2: combine tile stats -> g_m, g_rl. One thread per softmax row.
// ---------------------------------------------------------------------------
__global__ __launch_bounds__(256) void k_comb()
{
    const int r = blockIdx.x * 256 + threadIdx.x;   // [b][n][i]
    float M = -CUDART_INF_F, L = 0.f;
#pragma unroll 4
    for (int t = 0; t < NTJ; t++) {
        float m2 = g_tm[(size_t)t * NROWS + r];
        float l2 = g_tl[(size_t)t * NROWS + r];
        if (m2 > M) { L = L * __expf(M - m2) + l2; M = m2; }
        else        { L += l2 * __expf(m2 - M); }
    }
    const int i = r & (LL - 1);
    const int n = (r >> 11) & (NH - 1);
    const int b = r >> 15;
    g_m[((size_t)(b * LL + i)) * NH + n]  = M;
    g_rl[((size_t)(b * LL + i)) * NH + n] = 1.f / L;
}

// ---------------------------------------------------------------------------
// Kernel 3: normalize probs in place + context = P@V. (unchanged)
// ---------------------------------------------------------------------------
__global__ __launch_bounds__(512, 2) void k_pv(
    float* __restrict__ attn, const float* __restrict__ v,
    float* __restrict__ ctx)
{
    extern __shared__ float smem[];
    float* Ps = smem;             // [16 jj][16 n][20]
    float* Vs = Ps + 5120;        // [16 jj][16 n][64 d]
    float* Ms = Vs + 16384;       // [16 ii][16 n]
    float* Rs = Ms + 256;

    const int b  = blockIdx.y;
    const int i0 = blockIdx.x * 16;
    const int tid = threadIdx.x;

    if (tid < 256) {
        int ii = tid >> 4, nn = tid & 15;
        Ms[tid] = g_m[(size_t)(b * LL + i0 + ii) * NH + nn];
        Rs[tid] = g_rl[(size_t)(b * LL + i0 + ii) * NH + nn];
    }

    const int n  = tid >> 5;
    const int lane = tid & 31;
    const int dq = lane & 15;
    const int hs = lane >> 4;

    float4 acc[8];
#pragma unroll
    for (int r = 0; r < 8; r++) acc[r] = make_float4(0.f, 0.f, 0.f, 0.f);

    __syncthreads();

    for (int j0 = 0; j0 < LL; j0 += 16) {
        for (int idx = tid; idx < 4096; idx += 512) {
            int nn = idx & 15; int jj = (idx >> 4) & 15; int ii = idx >> 8;
            size_t g = (((size_t)(b * LL + i0 + ii)) * LL + j0 + jj) * NH + nn;
            float p = __expf(attn[g] - Ms[ii * 16 + nn]) * Rs[ii * 16 + nn];
            attn[g] = p;
            Ps[(jj * 16 + nn) * 20 + ii] = p;
        }
        for (int idx = tid; idx < 16384; idx += 512) {
            int d = idx & 63; int nn = (idx >> 6) & 15; int jj = idx >> 10;
            Vs[(jj * 16 + nn) * 64 + d] =
                v[(((size_t)(b * LL + j0 + jj)) * NH + nn) * DD + d];
        }
        __syncthreads();

#pragma unroll 4
        for (int jj = 0; jj < 16; jj++) {
            const float* pr = &Ps[(jj * 16 + n) * 20 + hs * 8];
            float4 p0 = *(const float4*)(pr);
            float4 p1 = *(const float4*)(pr + 4);
            float4 vv = *(const float4*)&Vs[(jj * 16 + n) * 64 + dq * 4];
            acc[0].x += p0.x * vv.x; acc[0].y += p0.x * vv.y; acc[0].z += p0.x * vv.z; acc[0].w += p0.x * vv.w;
            acc[1].x += p0.y * vv.x; acc[1].y += p0.y * vv.y; acc[1].z += p0.y * vv.z; acc[1].w += p0.y * vv.w;
            acc[2].x += p0.z * vv.x; acc[2].y += p0.z * vv.y; acc[2].z += p0.z * vv.z; acc[2].w += p0.z * vv.w;
            acc[3].x += p0.w * vv.x; acc[3].y += p0.w * vv.y; acc[3].z += p0.w * vv.z; acc[3].w += p0.w * vv.w;
            acc[4].x += p1.x * vv.x; acc[4].y += p1.x * vv.y; acc[4].z += p1.x * vv.z; acc[4].w += p1.x * vv.w;
            acc[5].x += p1.y * vv.x; acc[5].y += p1.y * vv.y; acc[5].z += p1.y * vv.z; acc[5].w += p1.y * vv.w;
            acc[6].x += p1.z * vv.x; acc[6].y += p1.z * vv.y; acc[6].z += p1.z * vv.z; acc[6].w += p1.z * vv.w;
            acc[7].x += p1.w * vv.x; acc[7].y += p1.w * vv.y; acc[7].z += p1.w * vv.z; acc[7].w += p1.w * vv.w;
        }
        __syncthreads();
    }

#pragma unroll
    for (int r = 0; r < 8; r++) {
        int ii = hs * 8 + r;
        size_t g = (((size_t)(b * LL + i0 + ii)) * NH + n) * DD + dq * 4;
        *(float4*)(ctx + g) = acc[r];
    }
}

// ---------------------------------------------------------------------------
extern "C" void kernel_launch(void* const* d_in, const int* in_sizes, int n_in,
                              void* d_out, int out_size)
{
    const float* q = (const float*)d_in[0];
    const float* k = (const float*)d_in[1];
    const float* v = (const float*)d_in[2];
    const int* mask = (const int*)d_in[3];

    float* ctx  = (float*)d_out;
    float* attn = (float*)d_out + (size_t)BB * LL * NH * DD;

    const int smem1 = 16384 * 4;                            // 64 KB
    const int smem3 = (5120 + 16384 + 256 + 256) * 4;       // ~88 KB
    cudaFuncSetAttribute(k_scores, cudaFuncAttributeMaxDynamicSharedMemorySize, smem1);
    cudaFuncSetAttribute(k_pv,     cudaFuncAttributeMaxDynamicSharedMemorySize, smem3);

    dim3 g1(LL / 32, LL / 32, BB * 2);
    k_scores<<<g1, 256, smem1>>>(q, k, mask, attn);

    k_comb<<<NROWS / 256, 256>>>();

    dim3 g3(LL / 16, BB);
    k_pv<<<g3, 512, smem3>>>(attn, v, ctx);
}